// round 13
// baseline (speedup 1.0000x reference)
#include <cuda_runtime.h>
#include <cstdint>

// SeparableConv3D: x[8,3,32,256,256] fp32, depthwise K=5 cross-correlation
// along W, then H, then T, zero 'same' padding each stage.
//
// R11 structure (best) + peeled loop + balanced item-B loads:
//   phase A: prefetch 2 x-rows into regs (item A: all threads; item B:
//            lanes 24-31 of EVERY warp), commit via aligned STS.128
//   phase B (lane=t, wg=w-quad): W-conv via 4 aligned LDS.64 + H-conv ring,
//            store s into pair-interleaved sbufP[p=w/2][t][2] (2x STS.64)
//   phase C (all 256 threads; (row, pair, t-quad)): T-conv = 4 LDS.128,
//            4x STG.64 coalesced
//   Loop split: warmup (3 iters, unrolled) / steady (branch-free) / final.
//   ONE __syncthreads per 2 h-rows.

#define NN 8
#define CC 3
#define TT 32
#define HH 256
#define WW 256
#define KK 5

#define WT 32                 // w outputs per block
#define HC 32                 // h rows per block -> grid = 24*8*8 = 1536
#define NIT ((HC + 4) / 2)    // 18 iterations of 2 rows
#define XSTRIDE 44            // x slab row stride (conflict-free)
#define PSTR 68               // sbufP per-pair stride (floats)

__global__ void __launch_bounds__(256, 4)
sepconv3d_fused(const float* __restrict__ x,
                const float* __restrict__ w1,   // along W
                const float* __restrict__ w2,   // along H
                const float* __restrict__ w3,   // along T
                float* __restrict__ out)
{
    __shared__ float xbuf[2][2][TT * XSTRIDE];       // [buf][row]
    __shared__ float sbufP[2][2][(WT / 2) * PSTR];   // [buf][row][pair][t][2]

    const int tid  = threadIdx.x;
    const int lane = tid & 31;     // phase B: = t
    const int wg   = tid >> 5;     // phase B: w-quad

    const int bid = blockIdx.x;               // 0..1535
    const int nc  = bid >> 6;                  // n*3+c
    const int rem = bid & 63;
    const int wt  = rem >> 3;                   // 0..7
    const int hcb = rem & 7;                    // 0..7
    const int c   = nc % CC;

    const int w0 = wt * WT;
    const int h0 = hcb * HC;
    const size_t HW = (size_t)HH * WW;

    const float wW0 = w1[c*KK+0], wW1 = w1[c*KK+1], wW2 = w1[c*KK+2], wW3 = w1[c*KK+3], wW4 = w1[c*KK+4];
    const float wH0 = w2[c*KK+0], wH1 = w2[c*KK+1], wH2 = w2[c*KK+2], wH3 = w2[c*KK+3], wH4 = w2[c*KK+4];
    const float wT0 = w3[c*KK+0], wT1 = w3[c*KK+1], wT2 = w3[c*KK+2], wT3 = w3[c*KK+3], wT4 = w3[c*KK+4];

    const float* xb = x   + (size_t)nc * (TT * HW);
    float*       ob = out + (size_t)nc * (TT * HW);

    // ---- slab-load geometry: item A = tid (all); item B = lanes 24-31/warp ----
    const int trA = tid / 10,  qA = tid - trA * 10;
    const bool hasB = (lane >= 24);
    const int iB  = 256 + wg * 8 + (lane - 24);       // 256..319 spread over warps
    const int trB = iB / 10,   qB = iB - trB * 10;
    const int gwA = w0 - 4 + 4 * qA;
    const int gwB = w0 - 4 + 4 * qB;
    const bool wvA = (gwA >= 0) && (gwA < WW);
    const bool wvB = hasB && (gwB >= 0) && (gwB < WW);
    const float* gA = xb + (size_t)trA * HW + (wvA ? gwA : 0);   // + h*WW
    const float* gB = xb + (size_t)trB * HW + (wvB ? gwB : 0);

    // smem commit addresses (aligned STS.128)
    float* const xsA00 = &xbuf[0][0][trA * XSTRIDE + 4 * qA];
    float* const xsA01 = &xbuf[0][1][trA * XSTRIDE + 4 * qA];
    float* const xsA10 = &xbuf[1][0][trA * XSTRIDE + 4 * qA];
    float* const xsA11 = &xbuf[1][1][trA * XSTRIDE + 4 * qA];
    float* const xsB00 = &xbuf[0][0][trB * XSTRIDE + 4 * qB];
    float* const xsB01 = &xbuf[0][1][trB * XSTRIDE + 4 * qB];
    float* const xsB10 = &xbuf[1][0][trB * XSTRIDE + 4 * qB];
    float* const xsB11 = &xbuf[1][1][trB * XSTRIDE + 4 * qB];

    // ---- phase C geometry: thread = (row rr, pair p, t-quad tq) ----
    const int rr  = tid >> 7;          // 0: threads 0-127, 1: threads 128-255
    const int idx = tid & 127;
    const int p   = idx & 15;          // w pair: w = w0 + 2p, 2p+1
    const int tq  = idx >> 4;          // 0..7
    const int t0  = 4 * tq;
    const int pbase = p * PSTR;
    const int q0off = pbase + max(2 * t0 - 4, 0);        // t0-2, t0-1  (x2 w)
    const int q1off = pbase + 2 * t0;                    // t0,   t0+1
    const int q2off = pbase + 2 * t0 + 4;                // t0+2, t0+3
    const int q3off = pbase + min(2 * t0 + 8, 2*TT - 8); // t0+4, t0+5 (clamped)
    const float mlo = (tq == 0) ? 0.f : 1.f;   // zero-pad t<0
    const float mhi = (tq == 7) ? 0.f : 1.f;   // zero-pad t>31
    float* op = ob + (size_t)t0 * HW + w0 + 2 * p
                   + (size_t)(h0 + rr) * WW - 6 * WW;

    // H-conv register ring: g1..g4 = W-conv of the last 4 input rows
    float4 g1 = {0,0,0,0}, g2 = {0,0,0,0}, g3 = {0,0,0,0}, g4 = {0,0,0,0};
    const int scolbase = 4 * wg;
    float* const sbP00 = &sbufP[0][0][(2 * wg) * PSTR + 2 * lane];
    float* const sbP01 = &sbufP[0][1][(2 * wg) * PSTR + 2 * lane];
    float* const sbP10 = &sbufP[1][0][(2 * wg) * PSTR + 2 * lane];
    float* const sbP11 = &sbufP[1][1][(2 * wg) * PSTR + 2 * lane];

    // ================= helper macros (textual, resolved per call site) =======
#define WCONV_ROWS(CUR)                                                        \
    {                                                                          \
        const float* row0 = &xbuf[CUR][0][lane * XSTRIDE + scolbase + 2];      \
        float2 a0 = *reinterpret_cast<const float2*>(row0);                    \
        float2 a1 = *reinterpret_cast<const float2*>(row0 + 2);                \
        float2 a2 = *reinterpret_cast<const float2*>(row0 + 4);                \
        float2 a3 = *reinterpret_cast<const float2*>(row0 + 6);                \
        r_a.x = wW0*a0.x + wW1*a0.y + wW2*a1.x + wW3*a1.y + wW4*a2.x;          \
        r_a.y = wW0*a0.y + wW1*a1.x + wW2*a1.y + wW3*a2.x + wW4*a2.y;          \
        r_a.z = wW0*a1.x + wW1*a1.y + wW2*a2.x + wW3*a2.y + wW4*a3.x;          \
        r_a.w = wW0*a1.y + wW1*a2.x + wW2*a2.y + wW3*a3.x + wW4*a3.y;          \
        const float* row1 = &xbuf[CUR][1][lane * XSTRIDE + scolbase + 2];      \
        float2 b0 = *reinterpret_cast<const float2*>(row1);                    \
        float2 b1 = *reinterpret_cast<const float2*>(row1 + 2);                \
        float2 b2 = *reinterpret_cast<const float2*>(row1 + 4);                \
        float2 b3 = *reinterpret_cast<const float2*>(row1 + 6);                \
        r_b.x = wW0*b0.x + wW1*b0.y + wW2*b1.x + wW3*b1.y + wW4*b2.x;          \
        r_b.y = wW0*b0.y + wW1*b1.x + wW2*b1.y + wW3*b2.x + wW4*b2.y;          \
        r_b.z = wW0*b1.x + wW1*b1.y + wW2*b2.x + wW3*b2.y + wW4*b3.x;          \
        r_b.w = wW0*b1.y + wW1*b2.x + wW2*b2.y + wW3*b3.x + wW4*b3.y;          \
    }

#define STORE_S(SA, SB)                                                        \
    {                                                                          \
        float sax = wH0*g1.x + wH1*g2.x + wH2*g3.x + wH3*g4.x + wH4*r_a.x;     \
        float say = wH0*g1.y + wH1*g2.y + wH2*g3.y + wH3*g4.y + wH4*r_a.y;     \
        float saz = wH0*g1.z + wH1*g2.z + wH2*g3.z + wH3*g4.z + wH4*r_a.z;     \
        float saw = wH0*g1.w + wH1*g2.w + wH2*g3.w + wH3*g4.w + wH4*r_a.w;     \
        *reinterpret_cast<float2*>(SA)        = make_float2(sax, say);         \
        *reinterpret_cast<float2*>(SA + PSTR) = make_float2(saz, saw);         \
        float sbx = wH0*g2.x + wH1*g3.x + wH2*g4.x + wH3*r_a.x + wH4*r_b.x;    \
        float sby = wH0*g2.y + wH1*g3.y + wH2*g4.y + wH3*r_a.y + wH4*r_b.y;    \
        float sbz = wH0*g2.z + wH1*g3.z + wH2*g4.z + wH3*r_a.z + wH4*r_b.z;    \
        float sbw = wH0*g2.w + wH1*g3.w + wH2*g4.w + wH3*r_a.w + wH4*r_b.w;    \
        *reinterpret_cast<float2*>(SB)        = make_float2(sbx, sby);         \
        *reinterpret_cast<float2*>(SB + PSTR) = make_float2(sbz, sbw);         \
    }

#define RING_SHIFT() { g1 = g3; g2 = g4; g3 = r_a; g4 = r_b; }

#define PHASE_C(SRCBUF)                                                        \
    {                                                                          \
        const float* sp = sbufP[SRCBUF][rr];                                   \
        float4 Q0 = *reinterpret_cast<const float4*>(sp + q0off);              \
        float4 Q1 = *reinterpret_cast<const float4*>(sp + q1off);              \
        float4 Q2 = *reinterpret_cast<const float4*>(sp + q2off);              \
        float4 Q3 = *reinterpret_cast<const float4*>(sp + q3off);              \
        Q0.x *= mlo; Q0.y *= mlo; Q0.z *= mlo; Q0.w *= mlo;                    \
        Q3.x *= mhi; Q3.y *= mhi; Q3.z *= mhi; Q3.w *= mhi;                    \
        float f0[8] = {Q0.x, Q0.z, Q1.x, Q1.z, Q2.x, Q2.z, Q3.x, Q3.z};        \
        float f1[8] = {Q0.y, Q0.w, Q1.y, Q1.w, Q2.y, Q2.w, Q3.y, Q3.w};        \
        _Pragma("unroll")                                                      \
        for (int k = 0; k < 4; ++k) {                                          \
            float2 o;                                                          \
            o.x = wT0*f0[k] + wT1*f0[k+1] + wT2*f0[k+2] + wT3*f0[k+3] + wT4*f0[k+4]; \
            o.y = wT0*f1[k] + wT1*f1[k+1] + wT2*f1[k+2] + wT3*f1[k+3] + wT4*f1[k+4]; \
            *reinterpret_cast<float2*>(op + (size_t)k * HW) = o;               \
        }                                                                      \
    }

#define COMMIT(CUR)                                                            \
    {                                                                          \
        *reinterpret_cast<float4*>((CUR) ? xsA00 : xsA10) = pa0;               \
        *reinterpret_cast<float4*>((CUR) ? xsA01 : xsA11) = pa1;               \
        if (hasB) {                                                            \
            *reinterpret_cast<float4*>((CUR) ? xsB00 : xsB10) = pb0;           \
            *reinterpret_cast<float4*>((CUR) ? xsB01 : xsB11) = pb1;           \
        }                                                                      \
    }
    // =========================================================================

    // ---- prologue: rows h0-2, h0-1 into xbuf[0][0..1] ----
    {
        float4 v0 = {0,0,0,0}, v1 = {0,0,0,0}, u0 = {0,0,0,0}, u1 = {0,0,0,0};
        if (wvA && h0 - 2 >= 0) v0 = *reinterpret_cast<const float4*>(gA + (size_t)(h0 - 2) * WW);
        if (wvA && h0 - 1 >= 0) v1 = *reinterpret_cast<const float4*>(gA + (size_t)(h0 - 1) * WW);
        *reinterpret_cast<float4*>(xsA00) = v0;
        *reinterpret_cast<float4*>(xsA01) = v1;
        if (hasB) {
            if (wvB && h0 - 2 >= 0) u0 = *reinterpret_cast<const float4*>(gB + (size_t)(h0 - 2) * WW);
            if (wvB && h0 - 1 >= 0) u1 = *reinterpret_cast<const float4*>(gB + (size_t)(h0 - 1) * WW);
            *reinterpret_cast<float4*>(xsB00) = u0;
            *reinterpret_cast<float4*>(xsB01) = u1;
        }
    }
    __syncthreads();

    // ---- warmup: ii = 0,1,2 (fully unrolled; no phase C) ----
    #pragma unroll
    for (int ii = 0; ii < 3; ++ii) {
        const int cur = ii & 1;
        float4 pa0 = {0,0,0,0}, pa1 = {0,0,0,0}, pb0 = {0,0,0,0}, pb1 = {0,0,0,0};
        {
            const int ha = h0 + 2 * ii;
            const int hb = ha + 1;
            if (wvA && ha < HH) pa0 = *reinterpret_cast<const float4*>(gA + (size_t)ha * WW);
            if (wvA && hb < HH) pa1 = *reinterpret_cast<const float4*>(gA + (size_t)hb * WW);
            if (wvB && ha < HH) pb0 = *reinterpret_cast<const float4*>(gB + (size_t)ha * WW);
            if (wvB && hb < HH) pb1 = *reinterpret_cast<const float4*>(gB + (size_t)hb * WW);
        }
        float4 r_a, r_b;
        WCONV_ROWS(cur)
        if (ii == 2) {
            float* sa = sbP00;   // ii=2 -> cur=0
            float* sb = sbP01;
            STORE_S(sa, sb)
        }
        RING_SHIFT()
        op += 2 * WW;
        COMMIT(cur)
        __syncthreads();
    }

    // ---- steady state: ii = 3 .. NIT-2 (branch-free body) ----
    #pragma unroll 2
    for (int ii = 3; ii < NIT - 1; ++ii) {
        const int cur = ii & 1;
        float4 pa0, pa1, pb0 = {0,0,0,0}, pb1 = {0,0,0,0};
        {
            const int ha = h0 + 2 * ii;      // always < HH here (ha <= h0+32... guard below)
            const int hb = ha + 1;
            // ha max = h0 + 2*(NIT-2) = h0 + 32; row h0+32 may be h=256 when hcb=7!
            const bool va = wvA && (ha < HH);
            const bool vb = wvA && (hb < HH);
            pa0 = va ? *reinterpret_cast<const float4*>(gA + (size_t)ha * WW) : make_float4(0,0,0,0);
            pa1 = vb ? *reinterpret_cast<const float4*>(gA + (size_t)hb * WW) : make_float4(0,0,0,0);
            if (wvB && ha < HH) pb0 = *reinterpret_cast<const float4*>(gB + (size_t)ha * WW);
            if (wvB && hb < HH) pb1 = *reinterpret_cast<const float4*>(gB + (size_t)hb * WW);
        }
        float4 r_a, r_b;
        WCONV_ROWS(cur)
        {
            float* sa = cur ? sbP10 : sbP00;
            float* sb = cur ? sbP11 : sbP01;
            STORE_S(sa, sb)
        }
        RING_SHIFT()
        PHASE_C(cur ^ 1)
        op += 2 * WW;
        COMMIT(cur)
        __syncthreads();
    }

    // ---- final iteration: ii = NIT-1 (no prefetch, no commit) ----
    {
        const int cur = (NIT - 1) & 1;   // = 1
        float4 r_a, r_b;
        WCONV_ROWS(cur)
        {
            float* sa = cur ? sbP10 : sbP00;
            float* sb = cur ? sbP11 : sbP01;
            STORE_S(sa, sb)
        }
        RING_SHIFT()
        PHASE_C(cur ^ 1)
        op += 2 * WW;
        __syncthreads();
    }

    // ---- epilogue: last 2 output rows from sbufP[(NIT-1)&1] ----
    PHASE_C((NIT - 1) & 1)

#undef WCONV_ROWS
#undef STORE_S
#undef RING_SHIFT
#undef PHASE_C
#undef COMMIT
}

extern "C" void kernel_launch(void* const* d_in, const int* in_sizes, int n_in,
                              void* d_out, int out_size)
{
    const float* x  = (const float*)d_in[0];
    const float* w1 = (const float*)d_in[1];
    const float* w2 = (const float*)d_in[2];
    const float* w3 = (const float*)d_in[3];
    float* out = (float*)d_out;

    // 24 (n*c) * 8 (w tiles) * 8 (h chunks) = 1536 blocks
    sepconv3d_fused<<<NN * CC * (WW / WT) * (HH / HC), 256>>>(x, w1, w2, w3, out);
}